// round 16
// baseline (speedup 1.0000x reference)
#include <cuda_runtime.h>
#include <math.h>

#define Bn 4
#define Cn 64
#define Hn 128
#define Wn 128
#define Pn 63
#define HW (Hn*Wn)
#define NG 16   /* channel groups of 4 */

// Scratch (static device globals)
__device__ __align__(16) float g_g0[Bn*Cn*HW];     // grad-act(c0)
__device__ __align__(16) float g_a1[Bn*HW];        // act(c1)
__device__ __align__(16) float g_part[NG*Bn*HW];   // channel-group partial sums

__constant__ float c_f0[Cn*25];
__constant__ float c_f1[Cn*25];
__constant__ float c_b0[Cn];
__constant__ float c_b1[1];

__device__ __forceinline__ float ex2f_(float x){ float r; asm("ex2.approx.f32 %0,%1;" : "=f"(r) : "f"(x)); return r; }
__device__ __forceinline__ float rcpf_(float x){ float r; asm("rcp.approx.f32 %0,%1;" : "=f"(r) : "f"(x)); return r; }

#define CJ1 0.60653065971f      /* exp(-1/2) */
#define CJ2 0.13533528324f      /* exp(-4/2) */
#define L2E 1.44269504089f

// 5-tap RBF via exp decomposition: exp(-(s-j)^2/2) = E0 * r^j * c_j
__device__ __forceinline__ void rbf5(float v, const float* __restrict__ w,
                                     float& a_out, float& g_out) {
    float u  = fmaf(v, 0.1f, 31.0f);
    float pf = rintf(u);
    pf = fminf(fmaxf(pf, 2.0f), 60.0f);   // window [pc-2,pc+2] stays in [0,62]
    int   pc = (int)pf;
    float s  = u - pf;
    s = fminf(fmaxf(s, -9.0f), 9.0f);     // avoid inf*0 at extreme inputs
    float r  = ex2f_(s * L2E);
    float E0 = ex2f_(s * s * (-0.5f * L2E));
    float q  = rcpf_(r);
    float r2 = r*r;
    float q2 = q*q;
    float m, A, B;
    m = w[pc-2]*(CJ2*q2); A  = m;  B = m * -2.0f;
    m = w[pc-1]*(CJ1*q ); A += m;  B = fmaf(m, -1.0f, B);
    m = w[pc  ];          A += m;
    m = w[pc+1]*(CJ1*r ); A += m;  B = fmaf(m,  1.0f, B);
    m = w[pc+2]*(CJ2*r2); A += m;  B = fmaf(m,  2.0f, B);
    a_out = E0 * A;
    g_out = (-0.1f * E0) * fmaf(s, A, -B);
}

// kA (fused conv0+RBF+conv1-partials): 16-row full-width tile, 4 channels.
// Staging computes 2 channels per unit; accumulate uses 2-row x 4-col blocks
// with a 6-row sliding window. grid (8,4,16)=512.
__global__ void __launch_bounds__(256) kA_enc(const float* __restrict__ x,
                                              const float* __restrict__ w0) {
    __shared__ float xs[24][132];       // 255*x rows h0-4..h0+19 clamp, cols -2..129 clamp
    __shared__ float sa0[2][20][136];   // a0 planes for 2 staged channels
    __shared__ float sw0[4*63];
    int tid = threadIdx.x;
    int h0 = blockIdx.x * 16;
    int b  = blockIdx.y;
    int g  = blockIdx.z;

    for (int i = tid; i < 4*63; i += 256) sw0[i] = w0[(g*4)*63 + i];
    const float* xb = x + b*HW;
    for (int i = tid; i < 24*132; i += 256) {
        int r = i / 132, c = i - r*132;
        int gh = min(max(h0 - 4 + r, 0), Hn-1);
        int gw = min(max(c - 2, 0), Wn-1);
        (&xs[0][0])[i] = xb[gh*Wn + gw] * 255.0f;
    }

    float acc[2][4] = {{0,0,0,0},{0,0,0,0}};   // 2 rows x 4 cols
    int r2   = tid >> 5;            // 0..7 row pair -> out rows 2r2, 2r2+1
    int wcol = (tid & 31) * 4;      // out col base

    #pragma unroll 1
    for (int cc2 = 0; cc2 < 2; ++cc2) {
        int ca = g*4 + cc2*2;
        int cb = ca + 1;
        float biasa = c_b0[ca], biasb = c_b0[cb];
        __syncthreads();
        // a0 stage: 20 rows x 32 strips of 4 = 640 units, 2 channels per unit
        #pragma unroll 1
        for (int u = tid; u < 640; u += 256) {
            int ri = u >> 5;
            int s  = u & 31;
            int w  = s * 4;
            int hc = min(max(h0 - 2 + ri, 0), Hn-1);
            int xr = hc - h0 + 2;
            float aA[4] = {biasa, biasa, biasa, biasa};
            float aB[4] = {biasb, biasb, biasb, biasb};
            #pragma unroll
            for (int dy = 0; dy < 5; ++dy) {
                float4 va = *(const float4*)&xs[xr+dy][w];
                float4 vb = *(const float4*)&xs[xr+dy][w+4];
                float v[8] = {va.x, va.y, va.z, va.w, vb.x, vb.y, vb.z, vb.w};
                #pragma unroll
                for (int dx = 0; dx < 5; ++dx) {
                    float fa = c_f0[ca*25 + dy*5 + dx];
                    float fb = c_f0[cb*25 + dy*5 + dx];
                    #pragma unroll
                    for (int j = 0; j < 4; ++j) {
                        aA[j] = fmaf(v[dx+j], fa, aA[j]);
                        aB[j] = fmaf(v[dx+j], fb, aB[j]);
                    }
                }
            }
            const float* wra = &sw0[(cc2*2)*63];
            const float* wrb = &sw0[(cc2*2+1)*63];
            float actA[4], grdA[4], actB[4], grdB[4];
            #pragma unroll
            for (int j = 0; j < 4; ++j) rbf5(aA[j], wra, actA[j], grdA[j]);
            #pragma unroll
            for (int j = 0; j < 4; ++j) rbf5(aB[j], wrb, actB[j], grdB[j]);
            #pragma unroll
            for (int j = 0; j < 4; ++j) {
                sa0[0][ri][2+w+j] = actA[j];
                sa0[1][ri][2+w+j] = actB[j];
            }
            if (s == 0)  {
                sa0[0][ri][0] = actA[0]; sa0[0][ri][1] = actA[0];
                sa0[1][ri][0] = actB[0]; sa0[1][ri][1] = actB[0];
            }
            if (s == 31) {
                sa0[0][ri][130] = actA[3]; sa0[0][ri][131] = actA[3];
                sa0[1][ri][130] = actB[3]; sa0[1][ri][131] = actB[3];
            }
            if (ri >= 2 && ri <= 17) {
                size_t base = (size_t)b*Cn*HW + (size_t)(h0 + ri - 2)*Wn + w;
                *(float4*)&g_g0[base + (size_t)ca*HW]
                    = make_float4(grdA[0], grdA[1], grdA[2], grdA[3]);
                *(float4*)&g_g0[base + (size_t)cb*HW]
                    = make_float4(grdB[0], grdB[1], grdB[2], grdB[3]);
            }
        }
        __syncthreads();
        // conv1 accumulate: 2-row x 4-col block per thread, 6-row sliding window
        #pragma unroll
        for (int ch = 0; ch < 2; ++ch) {
            int c = ca + ch;
            #pragma unroll
            for (int iy = 0; iy < 6; ++iy) {
                float4 va = *(const float4*)&sa0[ch][2*r2 + iy][wcol];
                float4 vb = *(const float4*)&sa0[ch][2*r2 + iy][wcol + 4];
                float v[8] = {va.x, va.y, va.z, va.w, vb.x, vb.y, vb.z, vb.w};
                if (iy < 5) {
                    #pragma unroll
                    for (int kx = 0; kx < 5; ++kx) {
                        float f = c_f1[c*25 + iy*5 + kx];
                        #pragma unroll
                        for (int j = 0; j < 4; ++j)
                            acc[0][j] = fmaf(v[kx+j], f, acc[0][j]);
                    }
                }
                if (iy > 0) {
                    #pragma unroll
                    for (int kx = 0; kx < 5; ++kx) {
                        float f = c_f1[c*25 + (iy-1)*5 + kx];
                        #pragma unroll
                        for (int j = 0; j < 4; ++j)
                            acc[1][j] = fmaf(v[kx+j], f, acc[1][j]);
                    }
                }
            }
        }
    }
    #pragma unroll
    for (int k = 0; k < 2; ++k) {
        int row = 2*r2 + k;
        *(float4*)&g_part[(size_t)g*(Bn*HW) + b*HW + (h0+row)*Wn + wcol]
            = make_float4(acc[k][0], acc[k][1], acc[k][2], acc[k][3]);
    }
}

// K2b: a1 = act(sum(partials) + b1, w1) — 128 CTAs x 512 thr = 1 wave
__global__ void __launch_bounds__(512) k2b_reduce_act(const float* __restrict__ w1) {
    __shared__ float sw[Pn];
    int tid = threadIdx.x;
    if (tid < Pn) sw[tid] = w1[tid];
    __syncthreads();
    int p = blockIdx.x * 512 + tid;
    float s = c_b1[0];
    #pragma unroll
    for (int g = 0; g < NG; ++g) s += g_part[g*(Bn*HW) + p];
    float a, gr;
    rbf5(s, sw, a, gr);
    g_a1[p] = a;
}

// K5 (fused deconv1*g0 + deconv0-partials): 16-row full-width tile, 4 channels.
// d-stage computes 2 channels per unit; accumulate uses 2-row x 4-col blocks.
__global__ void __launch_bounds__(256) k5_fused_deconv() {
    __shared__ float sa1[24][136];     // a1 rows h0-4..h0+19, cols -4..131, zero pad
    __shared__ float sd[2][20][132];   // d planes for 2 staged channels
    int tid = threadIdx.x;
    int h0 = blockIdx.x * 16;
    int b  = blockIdx.y;
    int g  = blockIdx.z;
    const float* ab = g_a1 + b*HW;

    for (int i = tid; i < 24*136; i += 256) {
        int r = i / 136, c = i - r*136;
        int gh = h0 - 4 + r, gw = c - 4;
        (&sa1[0][0])[i] = ((unsigned)gh < (unsigned)Hn && (unsigned)gw < (unsigned)Wn)
                          ? ab[gh*Wn + gw] : 0.f;
    }

    float acc[2][4] = {{0,0,0,0},{0,0,0,0}};   // 2 rows x 4 cols
    int r2   = tid >> 5;
    int wcol = (tid & 31) * 4;

    #pragma unroll 1
    for (int cc2 = 0; cc2 < 2; ++cc2) {
        int ca = g*4 + cc2*2;
        int cb = ca + 1;
        const float* g0a = g_g0 + (size_t)(b*Cn + ca)*HW;
        const float* g0b = g_g0 + (size_t)(b*Cn + cb)*HW;
        __syncthreads();
        // d stage: 20 rows x 33 strips of 4 = 660 units, 2 channels per unit
        #pragma unroll 1
        for (int u = tid; u < 660; u += 256) {
            int r  = u / 33;
            int s  = u - r*33;
            int c0 = s * 4;                 // sd col base; d col = c0-2+j
            int hd = h0 - 2 + r;
            float dA[4] = {0.f, 0.f, 0.f, 0.f};
            float dB[4] = {0.f, 0.f, 0.f, 0.f};
            #pragma unroll
            for (int ky = 0; ky < 5; ++ky) {
                float4 va = *(const float4*)&sa1[r+ky][c0];
                float4 vb = *(const float4*)&sa1[r+ky][c0+4];
                float v[8] = {va.x, va.y, va.z, va.w, vb.x, vb.y, vb.z, vb.w};
                #pragma unroll
                for (int kx = 0; kx < 5; ++kx) {
                    float fa = c_f1[ca*25 + 24 - (ky*5 + kx)];
                    float fb = c_f1[cb*25 + 24 - (ky*5 + kx)];
                    #pragma unroll
                    for (int j = 0; j < 4; ++j) {
                        dA[j] = fmaf(v[kx+j], fa, dA[j]);
                        dB[j] = fmaf(v[kx+j], fb, dB[j]);
                    }
                }
            }
            bool rv = (unsigned)hd < (unsigned)Hn;
            int hs = min(max(hd, 0), Hn-1);
            const float* ga = g0a + hs*Wn;
            const float* gb = g0b + hs*Wn;
            int w0c = c0 - 2;
            #pragma unroll
            for (int j = 0; j < 4; ++j) {
                int wj = min(max(w0c + j, 0), Wn-1);
                bool ok = rv && (unsigned)(w0c + j) < (unsigned)Wn;
                sd[0][r][c0+j] = ok ? dA[j] * ga[wj] : 0.f;
                sd[1][r][c0+j] = ok ? dB[j] * gb[wj] : 0.f;
            }
        }
        __syncthreads();
        // deconv0 accumulate: 2-row x 4-col block per thread, 6-row window
        #pragma unroll
        for (int ch = 0; ch < 2; ++ch) {
            int c = ca + ch;
            #pragma unroll
            for (int iy = 0; iy < 6; ++iy) {
                float4 va = *(const float4*)&sd[ch][2*r2 + iy][wcol];
                float4 vb = *(const float4*)&sd[ch][2*r2 + iy][wcol + 4];
                float v[8] = {va.x, va.y, va.z, va.w, vb.x, vb.y, vb.z, vb.w};
                if (iy < 5) {
                    #pragma unroll
                    for (int kx = 0; kx < 5; ++kx) {
                        float f = c_f0[c*25 + 24 - (iy*5 + kx)];
                        #pragma unroll
                        for (int j = 0; j < 4; ++j)
                            acc[0][j] = fmaf(v[kx+j], f, acc[0][j]);
                    }
                }
                if (iy > 0) {
                    #pragma unroll
                    for (int kx = 0; kx < 5; ++kx) {
                        float f = c_f0[c*25 + 24 - ((iy-1)*5 + kx)];
                        #pragma unroll
                        for (int j = 0; j < 4; ++j)
                            acc[1][j] = fmaf(v[kx+j], f, acc[1][j]);
                    }
                }
            }
        }
    }
    #pragma unroll
    for (int k = 0; k < 2; ++k) {
        int row = 2*r2 + k;
        *(float4*)&g_part[(size_t)g*(Bn*HW) + b*HW + (h0+row)*Wn + wcol]
            = make_float4(acc[k][0], acc[k][1], acc[k][2], acc[k][3]);
    }
}

// K4b: out = x - sum(partials)/255 - exp(lam)*(x - y) — 128 CTAs x 512 thr
__global__ void __launch_bounds__(512) k4b_reduce_out(const float* __restrict__ x,
                               const float* __restrict__ y,
                               const float* __restrict__ lam_param,
                               float* __restrict__ out) {
    int p = blockIdx.x * 512 + threadIdx.x;
    float s = 0.f;
    #pragma unroll
    for (int g = 0; g < NG; ++g) s += g_part[g*(Bn*HW) + p];
    float e  = __expf(lam_param[0]);
    float xv = x[p], yv = y[p];
    out[p] = xv - s*(1.0f/255.0f) - e*(xv - yv);
}

extern "C" void kernel_launch(void* const* d_in, const int* in_sizes, int n_in,
                              void* d_out, int out_size) {
    const float* x   = (const float*)d_in[0];
    const float* y   = (const float*)d_in[1];
    // d_in[2] = lam (ignored)
    const float* f0  = (const float*)d_in[3];
    const float* b0  = (const float*)d_in[4];
    const float* f1  = (const float*)d_in[5];
    const float* b1  = (const float*)d_in[6];
    const float* w0  = (const float*)d_in[7];
    const float* w1  = (const float*)d_in[8];
    const float* lam = (const float*)d_in[9];
    float* out = (float*)d_out;

    // Max shared-memory carveout so >=4 CTAs/SM fit (35KB smem each):
    // 512-CTA grids become single-wave (148*4=592 slots) with deeper
    // per-SM overlap across the staging<->accumulate syncs.
    // Host-side attribute set: idempotent, allocation-free, capture-safe.
    cudaFuncSetAttribute((const void*)kA_enc,
                         cudaFuncAttributePreferredSharedMemoryCarveout, 100);
    cudaFuncSetAttribute((const void*)k5_fused_deconv,
                         cudaFuncAttributePreferredSharedMemoryCarveout, 100);

    cudaMemcpyToSymbolAsync(c_f0, f0, Cn*25*sizeof(float), 0, cudaMemcpyDeviceToDevice, 0);
    cudaMemcpyToSymbolAsync(c_f1, f1, Cn*25*sizeof(float), 0, cudaMemcpyDeviceToDevice, 0);
    cudaMemcpyToSymbolAsync(c_b0, b0, Cn*sizeof(float),    0, cudaMemcpyDeviceToDevice, 0);
    cudaMemcpyToSymbolAsync(c_b1, b1, sizeof(float),       0, cudaMemcpyDeviceToDevice, 0);

    dim3 gT(Hn/16, Bn, NG);        // (8, 4, 16) = 512 CTAs
    dim3 gR(Bn*HW/512);            // (128) — one wave on 148 SMs

    kA_enc<<<gT, 256>>>(x, w0);
    k2b_reduce_act<<<gR, 512>>>(w1);
    k5_fused_deconv<<<gT, 256>>>();
    k4b_reduce_out<<<gR, 512>>>(x, y, lam, out);
}

// round 17
// speedup vs baseline: 1.0759x; 1.0759x over previous
#include <cuda_runtime.h>
#include <math.h>

#define Bn 4
#define Cn 64
#define Hn 128
#define Wn 128
#define Pn 63
#define HW (Hn*Wn)
#define NG 16   /* channel groups of 4 */

// Scratch (static device globals)
__device__ __align__(16) float g_g0[Bn*Cn*HW];     // grad-act(c0)
__device__ __align__(16) float g_a1[Bn*HW];        // act(c1)
__device__ __align__(16) float g_part[NG*Bn*HW];   // channel-group partial sums

__constant__ float c_f0[Cn*25];
__constant__ float c_f1[Cn*25];
__constant__ float c_b0[Cn];
__constant__ float c_b1[1];

__device__ __forceinline__ float ex2f_(float x){ float r; asm("ex2.approx.f32 %0,%1;" : "=f"(r) : "f"(x)); return r; }
__device__ __forceinline__ float rcpf_(float x){ float r; asm("rcp.approx.f32 %0,%1;" : "=f"(r) : "f"(x)); return r; }

#define CJ1 0.60653065971f      /* exp(-1/2) */
#define CJ2 0.13533528324f      /* exp(-4/2) */
#define L2E 1.44269504089f

// 5-tap RBF via exp decomposition: exp(-(s-j)^2/2) = E0 * r^j * c_j
__device__ __forceinline__ void rbf5(float v, const float* __restrict__ w,
                                     float& a_out, float& g_out) {
    float u  = fmaf(v, 0.1f, 31.0f);
    float pf = rintf(u);
    pf = fminf(fmaxf(pf, 2.0f), 60.0f);   // window [pc-2,pc+2] stays in [0,62]
    int   pc = (int)pf;
    float s  = u - pf;
    s = fminf(fmaxf(s, -9.0f), 9.0f);     // avoid inf*0 at extreme inputs
    float r  = ex2f_(s * L2E);
    float E0 = ex2f_(s * s * (-0.5f * L2E));
    float q  = rcpf_(r);
    float r2 = r*r;
    float q2 = q*q;
    float m, A, B;
    m = w[pc-2]*(CJ2*q2); A  = m;  B = m * -2.0f;
    m = w[pc-1]*(CJ1*q ); A += m;  B = fmaf(m, -1.0f, B);
    m = w[pc  ];          A += m;
    m = w[pc+1]*(CJ1*r ); A += m;  B = fmaf(m,  1.0f, B);
    m = w[pc+2]*(CJ2*r2); A += m;  B = fmaf(m,  2.0f, B);
    a_out = E0 * A;
    g_out = (-0.1f * E0) * fmaf(s, A, -B);
}

// Dynamic smem sizes (floats)
#define KA_XS     (24*132)
#define KA_SA0    (4*20*136)
#define KA_SW0    (4*63)
#define KA_SMEMF  (KA_XS + KA_SA0 + KA_SW0)            /* 14300 floats = 57200 B */
#define K5_SA1    (24*136)
#define K5_SD     (4*20*132)
#define K5_SMEMF  (K5_SA1 + K5_SD)                     /* 13824 floats = 55296 B */

// kA (fused conv0+RBF+conv1-partials): 16-row full-width tile, 4 channels.
// Staging computes ALL 4 channels per unit (10 LDS.128 feed 400 FMAs);
// accumulate uses 2-row x 4-col blocks with 6-row sliding window.
__global__ void __launch_bounds__(256, 3) kA_enc(const float* __restrict__ x,
                                                 const float* __restrict__ w0) {
    extern __shared__ float sm[];
    float* xs  = sm;                    // [24][132]
    float* sa0 = sm + KA_XS;            // [4][20][136]
    float* sw0 = sm + KA_XS + KA_SA0;   // [4*63]
#define XS(r,c)     xs[(r)*132 + (c)]
#define SA0(p,r,c)  sa0[((p)*20 + (r))*136 + (c)]
    int tid = threadIdx.x;
    int h0 = blockIdx.x * 16;
    int b  = blockIdx.y;
    int g  = blockIdx.z;

    for (int i = tid; i < 4*63; i += 256) sw0[i] = w0[(g*4)*63 + i];
    const float* xb = x + b*HW;
    for (int i = tid; i < 24*132; i += 256) {
        int r = i / 132, c = i - r*132;
        int gh = min(max(h0 - 4 + r, 0), Hn-1);
        int gw = min(max(c - 2, 0), Wn-1);
        xs[i] = xb[gh*Wn + gw] * 255.0f;
    }
    __syncthreads();

    // a0 stage: 20 rows x 32 strips of 4 = 640 units, 4 channels per unit
    #pragma unroll 1
    for (int u = tid; u < 640; u += 256) {
        int ri = u >> 5;
        int s  = u & 31;
        int w  = s * 4;
        int hc = min(max(h0 - 2 + ri, 0), Hn-1);
        int xr = hc - h0 + 2;
        float a[4][4];
        #pragma unroll
        for (int ch = 0; ch < 4; ++ch) {
            float bv = c_b0[g*4 + ch];
            #pragma unroll
            for (int j = 0; j < 4; ++j) a[ch][j] = bv;
        }
        #pragma unroll
        for (int dy = 0; dy < 5; ++dy) {
            float4 va = *(const float4*)&XS(xr+dy, w);
            float4 vb = *(const float4*)&XS(xr+dy, w+4);
            float v[8] = {va.x, va.y, va.z, va.w, vb.x, vb.y, vb.z, vb.w};
            #pragma unroll
            for (int dx = 0; dx < 5; ++dx) {
                #pragma unroll
                for (int ch = 0; ch < 4; ++ch) {
                    float f = c_f0[(g*4 + ch)*25 + dy*5 + dx];
                    #pragma unroll
                    for (int j = 0; j < 4; ++j)
                        a[ch][j] = fmaf(v[dx+j], f, a[ch][j]);
                }
            }
        }
        bool interior = (ri >= 2 && ri <= 17);
        size_t gbase = (size_t)b*Cn*HW + (size_t)(h0 + ri - 2)*Wn + w;
        #pragma unroll
        for (int ch = 0; ch < 4; ++ch) {
            const float* wr = &sw0[ch*63];
            float act[4], grd[4];
            #pragma unroll
            for (int j = 0; j < 4; ++j) rbf5(a[ch][j], wr, act[j], grd[j]);
            #pragma unroll
            for (int j = 0; j < 4; ++j) SA0(ch, ri, 2+w+j) = act[j];
            if (s == 0)  { SA0(ch, ri, 0)   = act[0]; SA0(ch, ri, 1)   = act[0]; }
            if (s == 31) { SA0(ch, ri, 130) = act[3]; SA0(ch, ri, 131) = act[3]; }
            if (interior) {
                *(float4*)&g_g0[gbase + (size_t)(g*4 + ch)*HW]
                    = make_float4(grd[0], grd[1], grd[2], grd[3]);
            }
        }
    }
    __syncthreads();

    // conv1 accumulate: 2-row x 4-col block per thread, 6-row sliding window
    float acc[2][4] = {{0,0,0,0},{0,0,0,0}};
    int r2   = tid >> 5;
    int wcol = (tid & 31) * 4;
    #pragma unroll
    for (int ch = 0; ch < 4; ++ch) {
        int c = g*4 + ch;
        #pragma unroll
        for (int iy = 0; iy < 6; ++iy) {
            float4 va = *(const float4*)&SA0(ch, 2*r2 + iy, wcol);
            float4 vb = *(const float4*)&SA0(ch, 2*r2 + iy, wcol + 4);
            float v[8] = {va.x, va.y, va.z, va.w, vb.x, vb.y, vb.z, vb.w};
            if (iy < 5) {
                #pragma unroll
                for (int kx = 0; kx < 5; ++kx) {
                    float f = c_f1[c*25 + iy*5 + kx];
                    #pragma unroll
                    for (int j = 0; j < 4; ++j)
                        acc[0][j] = fmaf(v[kx+j], f, acc[0][j]);
                }
            }
            if (iy > 0) {
                #pragma unroll
                for (int kx = 0; kx < 5; ++kx) {
                    float f = c_f1[c*25 + (iy-1)*5 + kx];
                    #pragma unroll
                    for (int j = 0; j < 4; ++j)
                        acc[1][j] = fmaf(v[kx+j], f, acc[1][j]);
                }
            }
        }
    }
    #pragma unroll
    for (int k = 0; k < 2; ++k) {
        int row = 2*r2 + k;
        *(float4*)&g_part[(size_t)g*(Bn*HW) + b*HW + (h0+row)*Wn + wcol]
            = make_float4(acc[k][0], acc[k][1], acc[k][2], acc[k][3]);
    }
#undef XS
#undef SA0
}

// K2b: a1 = act(sum(partials) + b1, w1) — 128 CTAs x 512 thr = 1 wave
__global__ void __launch_bounds__(512) k2b_reduce_act(const float* __restrict__ w1) {
    __shared__ float sw[Pn];
    int tid = threadIdx.x;
    if (tid < Pn) sw[tid] = w1[tid];
    __syncthreads();
    int p = blockIdx.x * 512 + tid;
    float s = c_b1[0];
    #pragma unroll
    for (int g = 0; g < NG; ++g) s += g_part[g*(Bn*HW) + p];
    float a, gr;
    rbf5(s, sw, a, gr);
    g_a1[p] = a;
}

// K5 (fused deconv1*g0 + deconv0-partials): 16-row full-width tile, 4 channels.
// d-stage computes ALL 4 channels per unit; accumulate 2-row x 4-col blocks.
__global__ void __launch_bounds__(256, 3) k5_fused_deconv() {
    extern __shared__ float sm[];
    float* sa1 = sm;                    // [24][136]
    float* sd  = sm + K5_SA1;           // [4][20][132]
#define SA1(r,c)   sa1[(r)*136 + (c)]
#define SD(p,r,c)  sd[((p)*20 + (r))*132 + (c)]
    int tid = threadIdx.x;
    int h0 = blockIdx.x * 16;
    int b  = blockIdx.y;
    int g  = blockIdx.z;
    const float* ab = g_a1 + b*HW;

    for (int i = tid; i < 24*136; i += 256) {
        int r = i / 136, c = i - r*136;
        int gh = h0 - 4 + r, gw = c - 4;
        sa1[i] = ((unsigned)gh < (unsigned)Hn && (unsigned)gw < (unsigned)Wn)
                 ? ab[gh*Wn + gw] : 0.f;
    }
    __syncthreads();

    // d stage: 20 rows x 33 strips of 4 = 660 units, 4 channels per unit
    #pragma unroll 1
    for (int u = tid; u < 660; u += 256) {
        int r  = u / 33;
        int s  = u - r*33;
        int c0 = s * 4;                 // sd col base; d col = c0-2+j
        int hd = h0 - 2 + r;
        float d[4][4];
        #pragma unroll
        for (int ch = 0; ch < 4; ++ch)
            #pragma unroll
            for (int j = 0; j < 4; ++j) d[ch][j] = 0.f;
        #pragma unroll
        for (int ky = 0; ky < 5; ++ky) {
            float4 va = *(const float4*)&SA1(r+ky, c0);
            float4 vb = *(const float4*)&SA1(r+ky, c0+4);
            float v[8] = {va.x, va.y, va.z, va.w, vb.x, vb.y, vb.z, vb.w};
            #pragma unroll
            for (int kx = 0; kx < 5; ++kx) {
                #pragma unroll
                for (int ch = 0; ch < 4; ++ch) {
                    float f = c_f1[(g*4 + ch)*25 + 24 - (ky*5 + kx)];
                    #pragma unroll
                    for (int j = 0; j < 4; ++j)
                        d[ch][j] = fmaf(v[kx+j], f, d[ch][j]);
                }
            }
        }
        bool rv = (unsigned)hd < (unsigned)Hn;
        int hs = min(max(hd, 0), Hn-1);
        int w0c = c0 - 2;
        #pragma unroll
        for (int j = 0; j < 4; ++j) {
            int wj = min(max(w0c + j, 0), Wn-1);
            bool ok = rv && (unsigned)(w0c + j) < (unsigned)Wn;
            #pragma unroll
            for (int ch = 0; ch < 4; ++ch) {
                const float* g0c = g_g0 + (size_t)(b*Cn + g*4 + ch)*HW + hs*Wn;
                SD(ch, r, c0+j) = ok ? d[ch][j] * g0c[wj] : 0.f;
            }
        }
    }
    __syncthreads();

    // deconv0 accumulate: 2-row x 4-col block per thread, 6-row window
    float acc[2][4] = {{0,0,0,0},{0,0,0,0}};
    int r2   = tid >> 5;
    int wcol = (tid & 31) * 4;
    #pragma unroll
    for (int ch = 0; ch < 4; ++ch) {
        int c = g*4 + ch;
        #pragma unroll
        for (int iy = 0; iy < 6; ++iy) {
            float4 va = *(const float4*)&SD(ch, 2*r2 + iy, wcol);
            float4 vb = *(const float4*)&SD(ch, 2*r2 + iy, wcol + 4);
            float v[8] = {va.x, va.y, va.z, va.w, vb.x, vb.y, vb.z, vb.w};
            if (iy < 5) {
                #pragma unroll
                for (int kx = 0; kx < 5; ++kx) {
                    float f = c_f0[c*25 + 24 - (iy*5 + kx)];
                    #pragma unroll
                    for (int j = 0; j < 4; ++j)
                        acc[0][j] = fmaf(v[kx+j], f, acc[0][j]);
                }
            }
            if (iy > 0) {
                #pragma unroll
                for (int kx = 0; kx < 5; ++kx) {
                    float f = c_f0[c*25 + 24 - ((iy-1)*5 + kx)];
                    #pragma unroll
                    for (int j = 0; j < 4; ++j)
                        acc[1][j] = fmaf(v[kx+j], f, acc[1][j]);
                }
            }
        }
    }
    #pragma unroll
    for (int k = 0; k < 2; ++k) {
        int row = 2*r2 + k;
        *(float4*)&g_part[(size_t)g*(Bn*HW) + b*HW + (h0+row)*Wn + wcol]
            = make_float4(acc[k][0], acc[k][1], acc[k][2], acc[k][3]);
    }
#undef SA1
#undef SD
}

// K4b: out = x - sum(partials)/255 - exp(lam)*(x - y) — 128 CTAs x 512 thr
__global__ void __launch_bounds__(512) k4b_reduce_out(const float* __restrict__ x,
                               const float* __restrict__ y,
                               const float* __restrict__ lam_param,
                               float* __restrict__ out) {
    int p = blockIdx.x * 512 + threadIdx.x;
    float s = 0.f;
    #pragma unroll
    for (int g = 0; g < NG; ++g) s += g_part[g*(Bn*HW) + p];
    float e  = __expf(lam_param[0]);
    float xv = x[p], yv = y[p];
    out[p] = xv - s*(1.0f/255.0f) - e*(xv - yv);
}

extern "C" void kernel_launch(void* const* d_in, const int* in_sizes, int n_in,
                              void* d_out, int out_size) {
    const float* x   = (const float*)d_in[0];
    const float* y   = (const float*)d_in[1];
    // d_in[2] = lam (ignored)
    const float* f0  = (const float*)d_in[3];
    const float* b0  = (const float*)d_in[4];
    const float* f1  = (const float*)d_in[5];
    const float* b1  = (const float*)d_in[6];
    const float* w0  = (const float*)d_in[7];
    const float* w1  = (const float*)d_in[8];
    const float* lam = (const float*)d_in[9];
    float* out = (float*)d_out;

    // Dynamic smem opt-in (57.2KB / 55.3KB per CTA; 3 CTAs/SM at full carveout).
    // Host-side attribute sets: idempotent, allocation-free, capture-safe.
    cudaFuncSetAttribute((const void*)kA_enc,
                         cudaFuncAttributeMaxDynamicSharedMemorySize, KA_SMEMF*4);
    cudaFuncSetAttribute((const void*)k5_fused_deconv,
                         cudaFuncAttributeMaxDynamicSharedMemorySize, K5_SMEMF*4);
    cudaFuncSetAttribute((const void*)kA_enc,
                         cudaFuncAttributePreferredSharedMemoryCarveout, 100);
    cudaFuncSetAttribute((const void*)k5_fused_deconv,
                         cudaFuncAttributePreferredSharedMemoryCarveout, 100);

    cudaMemcpyToSymbolAsync(c_f0, f0, Cn*25*sizeof(float), 0, cudaMemcpyDeviceToDevice, 0);
    cudaMemcpyToSymbolAsync(c_f1, f1, Cn*25*sizeof(float), 0, cudaMemcpyDeviceToDevice, 0);
    cudaMemcpyToSymbolAsync(c_b0, b0, Cn*sizeof(float),    0, cudaMemcpyDeviceToDevice, 0);
    cudaMemcpyToSymbolAsync(c_b1, b1, sizeof(float),       0, cudaMemcpyDeviceToDevice, 0);

    dim3 gT(Hn/16, Bn, NG);        // (8, 4, 16) = 512 CTAs
    dim3 gR(Bn*HW/512);            // (128) — one wave on 148 SMs

    kA_enc<<<gT, 256, KA_SMEMF*4>>>(x, w0);
    k2b_reduce_act<<<gR, 512>>>(w1);
    k5_fused_deconv<<<gT, 256, K5_SMEMF*4>>>();
    k4b_reduce_out<<<gR, 512>>>(x, y, lam, out);
}